// round 5
// baseline (speedup 1.0000x reference)
#include <cuda_runtime.h>
#include <cuda_bf16.h>

#define C1SSIM 1.0e-4f
#define C2SSIM 9.0e-4f

// Gaussian window (WIN=11, sigma=1.5), precomputed; becomes FFMA immediates.
#define GW_INIT {0.00102838f, 0.00759876f, 0.03600076f, 0.10936076f, 0.21300551f, \
                 0.26601166f, 0.21300551f, 0.10936076f, 0.03600076f, 0.00759876f, 0.00102838f}

// scratch (allocation-free: __device__ globals). +16 pad: conv window over-read.
__device__ __align__(16) float d_qn[15 * 64 * 441 + 16];  // normalized queries [b][c][p]
__device__ __align__(16) float d_sn[25 * 64 * 441 + 16];  // normalized supports [ns][c][p]
__device__ float d_mu[40 * 64 * 121];                      // gaussian mean per image-channel
__device__ float d_sg[40 * 64 * 121];                      // variance E[x^2]-mu^2
__device__ __align__(16) float d_part[75 * 64];            // per (b,n,c) ssim-sum
__device__ int d_count;                                    // completion counter (self-resetting)

// K1: per-position channel L2-normalize + transpose (p,c)->(c,p).
// Thread = one spatial position; 64 channels in registers via float4.
__global__ void k_norm2(const float* __restrict__ x1, const float* __restrict__ x2) {
    int img = blockIdx.x;                      // 0..39
    int p = blockIdx.y * 64 + threadIdx.x;     // position
    if (p >= 441) return;
    const float* src = (img < 15) ? (x1 + img * 441 * 64) : (x2 + (img - 15) * 441 * 64);
    float* dst = (img < 15) ? (d_qn + img * 64 * 441) : (d_sn + (img - 15) * 64 * 441);

    const float4* s4 = (const float4*)(src + p * 64);
    float4 v[16];
    float ss = 0.f;
#pragma unroll
    for (int i = 0; i < 16; i++) {
        v[i] = s4[i];
        ss += v[i].x * v[i].x + v[i].y * v[i].y + v[i].z * v[i].z + v[i].w * v[i].w;
    }
    float inv = rsqrtf(ss);
#pragma unroll
    for (int i = 0; i < 16; i++) {
        dst[(4 * i + 0) * 441 + p] = v[i].x * inv;   // coalesced across p
        dst[(4 * i + 1) * 441 + p] = v[i].y * inv;
        dst[(4 * i + 2) * 441 + p] = v[i].z * inv;
        dst[(4 * i + 3) * 441 + p] = v[i].w * inv;
    }
}

// K2: warp-per-channel stats: separable gaussian of x and x^2 -> mu, sigma^2.
__global__ void k_stats2() {
    const float GW[11] = GW_INIT;
    __shared__ float x[4][448];
    __shared__ float h1[4][232];
    __shared__ float h2[4][232];
    int tid = threadIdx.x, w = tid >> 5, lane = tid & 31;
    int id = blockIdx.x * 4 + w;     // img*64 + c
    int img = id >> 6, c = id & 63;
    const float* row = (img < 15) ? (d_qn + (img * 64 + c) * 441)
                                  : (d_sn + ((img - 15) * 64 + c) * 441);
    float* xw = x[w]; float* h1w = h1[w]; float* h2w = h2[w];

    for (int i = lane; i < 441; i += 32) xw[i] = row[i];
    __syncwarp();
    for (int o = lane; o < 231; o += 32) {   // 21 rows x 11 cols
        int r = o / 11, j = o - 11 * r;
        const float* xr = xw + r * 21 + j;
        float s1 = 0.f, s2 = 0.f;
#pragma unroll
        for (int k = 0; k < 11; k++) { float v = xr[k]; s1 = fmaf(GW[k], v, s1); s2 = fmaf(GW[k] * v, v, s2); }
        h1w[o] = s1; h2w[o] = s2;
    }
    __syncwarp();
    for (int o = lane; o < 121; o += 32) {   // 11 x 11
        int i = o / 11, j = o - 11 * i;
        float m = 0.f, m2 = 0.f;
#pragma unroll
        for (int k = 0; k < 11; k++) {
            m  = fmaf(GW[k], h1w[(i + k) * 11 + j], m);
            m2 = fmaf(GW[k], h2w[(i + k) * 11 + j], m2);
        }
        d_mu[id * 121 + o] = m;
        d_sg[id * 121 + o] = m2 - m * m;
    }
}

// K3: block per (b,n,c); serial over 5 shots; multi-output sliding-window convs;
// fused device-wide final reduce in last-arriving block.
__global__ void k_cross3(float* __restrict__ out) {
    const float GW[11] = GW_INIT;
    int c = blockIdx.x, n = blockIdx.y, b = blockIdx.z;
    __shared__ float q[448];
    __shared__ float h[240];   // 231 used; padded for 13-wide window over-read
    __shared__ float red[4];
    __shared__ int is_last;
    int tid = threadIdx.x, w = tid >> 5, lane = tid & 31;

    const float* qrow = d_qn + (b * 64 + c) * 441;
    for (int i = tid; i < 448; i += 128) q[i] = (i < 441) ? qrow[i] : 0.f;

    // conv1 task map: tid<84: row r (0..20), group grp (0..3), outputs j0..j0+nout-1
    int r1 = tid >> 2, g1 = tid & 3;
    int j0 = g1 * 3, nout1 = (g1 == 3) ? 2 : 3;
    int base1 = r1 * 21 + j0;
    // conv2 task map: tid<44: col (0..10), group (0..3), output rows i0..i0+nout2-1
    int col = tid >> 2, g2 = tid & 3;
    int i0 = g2 * 3, nout2 = (g2 == 3) ? 2 : 3;
    int base2 = i0 * 11 + col;

    // preload query stats for this thread's conv2 outputs (same o every shot)
    float mu1r[3], sg1r[3];
    if (tid < 44) {
        const float* mu1p = d_mu + (b * 64 + c) * 121;
        const float* sg1p = d_sg + (b * 64 + c) * 121;
#pragma unroll
        for (int m = 0; m < 3; m++) {
            int o = (i0 + m) * 11 + col;
            if (m < nout2) { mu1r[m] = mu1p[o]; sg1r[m] = sg1p[o]; }
        }
    }
    __syncthreads();

    float acc = 0.f;
    for (int s = 0; s < 5; s++) {
        int ns = n * 5 + s;
        const float* srow = d_sn + (ns * 64 + c) * 441;
        const float* mu2p = d_mu + ((15 + ns) * 64 + c) * 121;
        const float* sg2p = d_sg + ((15 + ns) * 64 + c) * 121;

        // phase A: horizontal conv of q*s (fused elementwise product), 3 outputs/thread
        if (tid < 84) {
            float wv[13];
#pragma unroll
            for (int k = 0; k < 13; k++) wv[k] = q[base1 + k] * srow[base1 + k];
#pragma unroll
            for (int m = 0; m < 3; m++) {
                if (m < nout1) {
                    float sv = 0.f;
#pragma unroll
                    for (int k = 0; k < 11; k++) sv = fmaf(GW[k], wv[m + k], sv);
                    h[r1 * 11 + j0 + m] = sv;
                }
            }
        }
        __syncthreads();  // h ready; also fences red[] reuse from previous shot

        // phase B: vertical conv + SSIM, 3 outputs/thread
        float ws = 0.f;
        if (tid < 44) {
            float hw[13];
#pragma unroll
            for (int k = 0; k < 13; k++) hw[k] = h[base2 + k * 11];
#pragma unroll
            for (int m = 0; m < 3; m++) {
                if (m < nout2) {
                    float t12 = 0.f;
#pragma unroll
                    for (int k = 0; k < 11; k++) t12 = fmaf(GW[k], hw[m + k], t12);
                    int o = (i0 + m) * 11 + col;
                    float mu1 = mu1r[m], mu2 = mu2p[o];
                    float sg1 = sg1r[m], sg2 = sg2p[o];
                    float m12 = mu1 * mu2;
                    float num = (2.f * m12 + C1SSIM) * (2.f * (t12 - m12) + C2SSIM);
                    float den = (mu1 * mu1 + mu2 * mu2 + C1SSIM) * (sg1 + sg2 + C2SSIM);
                    ws += num / den;
                }
            }
        }
#pragma unroll
        for (int off = 16; off > 0; off >>= 1) ws += __shfl_down_sync(0xffffffffu, ws, off);
        if (lane == 0) red[w] = ws;
        __syncthreads();
        if (tid == 0) acc += red[0] + red[1] + red[2] + red[3];
        // next iteration's first __syncthreads protects h and red
    }

    if (tid == 0) {
        d_part[(b * 5 + n) * 64 + c] = acc;
        __threadfence();
        int old = atomicAdd(&d_count, 1);
        is_last = (old == 64 * 5 * 15 - 1) ? 1 : 0;
    }
    __syncthreads();

    if (is_last) {
        __threadfence();  // acquire: all blocks' d_part writes visible
        if (tid < 75) {
            const float4* p4 = (const float4*)(d_part + tid * 64);
            float ssum = 0.f;
#pragma unroll
            for (int k = 0; k < 16; k++) { float4 t = p4[k]; ssum += t.x + t.y + t.z + t.w; }
            out[tid] = ssum * (1.0f / (64.0f * 121.0f));
        }
        if (tid == 0) d_count = 0;  // self-reset for graph replay
    }
}

extern "C" void kernel_launch(void* const* d_in, const int* in_sizes, int n_in,
                              void* d_out, int out_size) {
    const float* x1 = (const float*)d_in[0];   // (15, 441, 64)
    const float* x2 = (const float*)d_in[1];   // (5, 5, 441, 64)
    float* out = (float*)d_out;                // (15, 5)

    dim3 g1(40, 7);
    k_norm2<<<g1, 64>>>(x1, x2);
    k_stats2<<<640, 128>>>();
    dim3 g3(64, 5, 15);
    k_cross3<<<g3, 128>>>(out);
}

// round 6
// speedup vs baseline: 1.2252x; 1.2252x over previous
#include <cuda_runtime.h>
#include <cuda_bf16.h>

#define C1SSIM 1.0e-4f
#define C2SSIM 9.0e-4f

// Gaussian window (WIN=11, sigma=1.5), precomputed; becomes FFMA immediates.
#define GW_INIT {0.00102838f, 0.00759876f, 0.03600076f, 0.10936076f, 0.21300551f, \
                 0.26601166f, 0.21300551f, 0.10936076f, 0.03600076f, 0.00759876f, 0.00102838f}

// scratch (allocation-free: __device__ globals). +16 pad: conv window over-read.
__device__ __align__(16) float d_qn[15 * 64 * 441 + 16];  // normalized queries [b][c][p]
__device__ __align__(16) float d_sn[25 * 64 * 441 + 16];  // normalized supports [ns][c][p]
__device__ float d_mu[40 * 64 * 121];                      // gaussian mean per image-channel
__device__ float d_sg[40 * 64 * 121];                      // variance E[x^2]-mu^2
__device__ __align__(16) float d_part[75 * 64];            // per (b,n,c) ssim-sum

// K1: per-position channel L2-normalize + transpose (p,c)->(c,p).
__global__ void k_norm2(const float* __restrict__ x1, const float* __restrict__ x2) {
    int img = blockIdx.x;                      // 0..39
    int p = blockIdx.y * 64 + threadIdx.x;     // position
    if (p >= 441) return;
    const float* src = (img < 15) ? (x1 + img * 441 * 64) : (x2 + (img - 15) * 441 * 64);
    float* dst = (img < 15) ? (d_qn + img * 64 * 441) : (d_sn + (img - 15) * 64 * 441);

    const float4* s4 = (const float4*)(src + p * 64);
    float4 v[16];
    float ss = 0.f;
#pragma unroll
    for (int i = 0; i < 16; i++) {
        v[i] = s4[i];
        ss += v[i].x * v[i].x + v[i].y * v[i].y + v[i].z * v[i].z + v[i].w * v[i].w;
    }
    float inv = rsqrtf(ss);
#pragma unroll
    for (int i = 0; i < 16; i++) {
        dst[(4 * i + 0) * 441 + p] = v[i].x * inv;   // coalesced across p
        dst[(4 * i + 1) * 441 + p] = v[i].y * inv;
        dst[(4 * i + 2) * 441 + p] = v[i].z * inv;
        dst[(4 * i + 3) * 441 + p] = v[i].w * inv;
    }
}

// K2: warp-per-channel stats: separable gaussian of x and x^2 -> mu, sigma^2.
__global__ void k_stats2() {
    const float GW[11] = GW_INIT;
    __shared__ float x[4][448];
    __shared__ float h1[4][232];
    __shared__ float h2[4][232];
    int tid = threadIdx.x, w = tid >> 5, lane = tid & 31;
    int id = blockIdx.x * 4 + w;     // img*64 + c
    int img = id >> 6, c = id & 63;
    const float* row = (img < 15) ? (d_qn + (img * 64 + c) * 441)
                                  : (d_sn + ((img - 15) * 64 + c) * 441);
    float* xw = x[w]; float* h1w = h1[w]; float* h2w = h2[w];

    for (int i = lane; i < 441; i += 32) xw[i] = row[i];
    __syncwarp();
    for (int o = lane; o < 231; o += 32) {   // 21 rows x 11 cols
        int r = o / 11, j = o - 11 * r;
        const float* xr = xw + r * 21 + j;
        float s1 = 0.f, s2 = 0.f;
#pragma unroll
        for (int k = 0; k < 11; k++) { float v = xr[k]; s1 = fmaf(GW[k], v, s1); s2 = fmaf(GW[k] * v, v, s2); }
        h1w[o] = s1; h2w[o] = s2;
    }
    __syncwarp();
    for (int o = lane; o < 121; o += 32) {   // 11 x 11
        int i = o / 11, j = o - 11 * i;
        float m = 0.f, m2 = 0.f;
#pragma unroll
        for (int k = 0; k < 11; k++) {
            m  = fmaf(GW[k], h1w[(i + k) * 11 + j], m);
            m2 = fmaf(GW[k], h2w[(i + k) * 11 + j], m2);
        }
        d_mu[id * 121 + o] = m;
        d_sg[id * 121 + o] = m2 - m * m;
    }
}

// K3: block per (b,n,c); serial shots; 2 barriers/shot; per-thread SSIM accumulator
// across shots, single block-reduce at the end. No atomics.
__global__ void k_cross4() {
    const float GW[11] = GW_INIT;
    int c = blockIdx.x, n = blockIdx.y, b = blockIdx.z;
    __shared__ float q[448];
    __shared__ float h[240];   // 231 used
    __shared__ float red[4];
    int tid = threadIdx.x, w = tid >> 5, lane = tid & 31;

    const float* qrow = d_qn + (b * 64 + c) * 441;
    for (int i = tid; i < 448; i += 128) q[i] = (i < 441) ? qrow[i] : 0.f;

    // phase A map: tid<126: row r1 (0..20), group g1 (0..5), outputs j0=g1*2 (+1)
    int r1 = tid / 6, g1 = tid - r1 * 6;
    int j0 = g1 * 2, nout1 = (g1 == 5) ? 1 : 2;
    int base1 = r1 * 21 + j0;
    // phase B map: tid<121: one output o=(i2,j2)
    int i2 = tid / 11, j2 = tid - i2 * 11;

    // preload query stats (same output every shot)
    float mu1 = 0.f, sg1 = 0.f;
    if (tid < 121) {
        mu1 = d_mu[(b * 64 + c) * 121 + tid];
        sg1 = d_sg[(b * 64 + c) * 121 + tid];
    }
    float mu1sq = mu1 * mu1;
    __syncthreads();

    float accv = 0.f;
#pragma unroll
    for (int s = 0; s < 5; s++) {
        int ns = n * 5 + s;
        const float* srow = d_sn + (ns * 64 + c) * 441;

        // phase A: horizontal conv of q*s, up to 2 outputs/thread
        if (tid < 126) {
            float wv[12];
#pragma unroll
            for (int k = 0; k < 12; k++) wv[k] = q[base1 + k] * srow[base1 + k];
            float sv0 = 0.f, sv1 = 0.f;
#pragma unroll
            for (int k = 0; k < 11; k++) {
                sv0 = fmaf(GW[k], wv[k], sv0);
                sv1 = fmaf(GW[k], wv[k + 1], sv1);
            }
            h[r1 * 11 + j0] = sv0;
            if (nout1 == 2) h[r1 * 11 + j0 + 1] = sv1;
        }
        __syncthreads();  // h ready

        // phase B: vertical conv + SSIM accumulate
        if (tid < 121) {
            const float* hb = h + i2 * 11 + j2;
            float t12 = 0.f;
#pragma unroll
            for (int k = 0; k < 11; k++) t12 = fmaf(GW[k], hb[k * 11], t12);
            int sbase = ((15 + ns) * 64 + c) * 121 + tid;
            float mu2 = d_mu[sbase], sg2 = d_sg[sbase];
            float m12 = mu1 * mu2;
            float num = (2.f * m12 + C1SSIM) * (2.f * (t12 - m12) + C2SSIM);
            float den = (mu1sq + mu2 * mu2 + C1SSIM) * (sg1 + sg2 + C2SSIM);
            accv += num / den;
        }
        __syncthreads();  // h consumed before next shot overwrites
    }

    // single block reduction
#pragma unroll
    for (int off = 16; off > 0; off >>= 1) accv += __shfl_down_sync(0xffffffffu, accv, off);
    if (lane == 0) red[w] = accv;
    __syncthreads();
    if (tid == 0) d_part[(b * 5 + n) * 64 + c] = red[0] + red[1] + red[2] + red[3];
}

// K4: reduce channels, scale by 1/(C*H'*W')
__global__ void k_final(float* __restrict__ out) {
    int o = blockIdx.x;  // 0..74 == b*5 + n
    const float4* p4 = (const float4*)(d_part + o * 64);
    float4 t = p4[threadIdx.x & 15];
    float v = t.x + t.y + t.z + t.w;   // 16 lanes cover 64 values
    v = (threadIdx.x < 16) ? v : 0.f;
#pragma unroll
    for (int off = 8; off > 0; off >>= 1) v += __shfl_down_sync(0xffffffffu, v, off);
    if (threadIdx.x == 0) out[o] = v * (1.0f / (64.0f * 121.0f));
}

extern "C" void kernel_launch(void* const* d_in, const int* in_sizes, int n_in,
                              void* d_out, int out_size) {
    const float* x1 = (const float*)d_in[0];   // (15, 441, 64)
    const float* x2 = (const float*)d_in[1];   // (5, 5, 441, 64)
    float* out = (float*)d_out;                // (15, 5)

    dim3 g1(40, 7);
    k_norm2<<<g1, 64>>>(x1, x2);
    k_stats2<<<640, 128>>>();
    dim3 g3(64, 5, 15);
    k_cross4<<<g3, 128>>>();
    k_final<<<75, 32>>>(out);
}